// round 2
// baseline (speedup 1.0000x reference)
#include <cuda_runtime.h>

// Problem constants (fixed by reference)
#define CC   54          // channels
#define CP   27          // channel pairs (54/2)
#define MM   6           // materials
#define TT   20          // temperatures
#define NCAND 120        // M*T candidates
#define C1F  1.191042e-8f
#define C2F  1.4387752f

// Device-global scratch (no allocations allowed)
__device__ __align__(16) unsigned long long g_cand2[CP * NCAND]; // packed (c2j, c2j+1), layout [j][k]
__device__ float  g_c2[NCAND];
__device__ float  g_tc[TT];
__device__ float  g_lm[MM];
__device__ double g_obj;

__device__ __forceinline__ unsigned long long pack2(float x, float y) {
    unsigned long long r;
    asm("mov.b64 %0, {%1,%2};" : "=l"(r) : "f"(x), "f"(y));
    return r;
}
__device__ __forceinline__ void unpack2(unsigned long long v, float& x, float& y) {
    asm("mov.b64 {%0,%1}, %2;" : "=f"(x), "=f"(y) : "l"(v));
}
__device__ __forceinline__ void fma2(unsigned long long& d, unsigned long long a, unsigned long long b) {
    // d = a * b + d  (packed f32x2, full fp32 precision per lane)
    asm("fma.rn.f32x2 %0, %1, %2, %0;" : "+l"(d) : "l"(a), "l"(b));
}

// ---------------------------------------------------------------------------
// Setup: build candidate spectra, norms, t_cand, lib means; zero accumulator.
// ---------------------------------------------------------------------------
__global__ void hadar_setup(const float* __restrict__ s_sky,
                            const float* __restrict__ s_ground,
                            const float* __restrict__ library,
                            const float* __restrict__ wg) {
    __shared__ float sh_xamb[CC];
    __shared__ float sh_B[TT][CC];
    __shared__ float sh_lib[MM][CC];
    int tid = threadIdx.x;
    if (tid == 0) g_obj = 0.0;
    for (int c = tid; c < CC; c += blockDim.x)
        sh_xamb[c] = 0.5f * s_sky[c] + 0.5f * s_ground[c];
    for (int i = tid; i < MM * CC; i += blockDim.x)
        sh_lib[i / CC][i % CC] = library[i];
    for (int i = tid; i < TT * CC; i += blockDim.x) {
        int t = i / CC, c = i % CC;
        float Tk = 250.0f + (100.0f / 19.0f) * (float)t;
        float nu = wg[c];
        sh_B[t][c] = C1F * nu * nu * nu / expm1f(C2F * nu / Tk);
    }
    if (tid < TT) g_tc[tid] = 250.0f + (100.0f / 19.0f) * (float)tid;
    __syncthreads();
    if (tid < MM) {
        float s = 0.0f;
        for (int c = 0; c < CC; c++) s += sh_lib[tid][c];
        g_lm[tid] = s / (float)CC;
    }
    // cand[k][c] = lib[m][c]*B[t][c] + (1-lib[m][c])*x_amb[c], k = m*TT + t
    for (int i = tid; i < NCAND * CP; i += blockDim.x) {
        int k = i / CP, j = i % CP;
        int m = k / TT, t = k % TT;
        int c0 = 2 * j;
        float e0 = sh_lib[m][c0], e1 = sh_lib[m][c0 + 1];
        float v0 = e0 * sh_B[t][c0]     + (1.0f - e0) * sh_xamb[c0];
        float v1 = e1 * sh_B[t][c0 + 1] + (1.0f - e1) * sh_xamb[c0 + 1];
        g_cand2[j * NCAND + k] = pack2(v0, v1);
    }
    for (int k = tid; k < NCAND; k += blockDim.x) {
        int m = k / TT, t = k % TT;
        float s = 0.0f;
        for (int c = 0; c < CC; c++) {
            float e = sh_lib[m][c];
            float v = e * sh_B[t][c] + (1.0f - e) * sh_xamb[c];
            s += v * v;
        }
        g_c2[k] = s;
    }
}

// ---------------------------------------------------------------------------
// Main: per-pixel argmin over 120 candidates + all array outputs.
// ---------------------------------------------------------------------------
__global__ __launch_bounds__(256)
void hadar_main(const float* __restrict__ s_obs,
                const float* __restrict__ library,
                float* __restrict__ out, int N) {
    __shared__ __align__(16) unsigned long long s_cand[CP * NCAND]; // ~25.9 KB
    __shared__ float s_c2v[NCAND];
    __shared__ float s_tc[TT];
    __shared__ float s_lm[MM];
    __shared__ float s_lib[MM * CC];
    __shared__ float red[256];

    int tid = threadIdx.x;
    for (int i = tid; i < CP * NCAND; i += 256) s_cand[i] = g_cand2[i];
    for (int i = tid; i < NCAND; i += 256) s_c2v[i] = g_c2[i];
    for (int i = tid; i < MM * CC; i += 256) s_lib[i] = library[i];
    if (tid < TT) s_tc[tid] = g_tc[tid];
    if (tid < MM) s_lm[tid] = g_lm[tid];
    __syncthreads();

    long long n = (long long)blockIdx.x * 256 + tid;
    float bl = 0.0f;

    if (n < N) {
        // Load s_obs row as 27 packed pairs; compute ||s||^2
        unsigned long long s2[CP];
        float s2sum = 0.0f;
        const float2* sp = (const float2*)(s_obs + n * CC);
#pragma unroll
        for (int j = 0; j < CP; j++) {
            float2 v = sp[j];
            s2sum = fmaf(v.x, v.x, fmaf(v.y, v.y, s2sum));
            s2[j] = pack2(v.x, v.y);
        }

        float minval = 3.402823e38f;
        int mink = 0;
#pragma unroll 1
        for (int k0 = 0; k0 < NCAND; k0 += 4) {
            unsigned long long a0 = 0ULL, a1 = 0ULL, a2 = 0ULL, a3 = 0ULL;
#pragma unroll
            for (int j = 0; j < CP; j++) {
                const ulonglong2* row = (const ulonglong2*)(s_cand + j * NCAND + k0);
                ulonglong2 p = row[0];
                ulonglong2 q = row[1];
                fma2(a0, s2[j], p.x);
                fma2(a1, s2[j], p.y);
                fma2(a2, s2[j], q.x);
                fma2(a3, s2[j], q.y);
            }
            float lo, hi, dot, val;
            unpack2(a0, lo, hi); dot = lo + hi;
            val = fmaf(-2.0f, dot, s_c2v[k0 + 0]);
            if (val < minval) { minval = val; mink = k0 + 0; }
            unpack2(a1, lo, hi); dot = lo + hi;
            val = fmaf(-2.0f, dot, s_c2v[k0 + 1]);
            if (val < minval) { minval = val; mink = k0 + 1; }
            unpack2(a2, lo, hi); dot = lo + hi;
            val = fmaf(-2.0f, dot, s_c2v[k0 + 2]);
            if (val < minval) { minval = val; mink = k0 + 2; }
            unpack2(a3, lo, hi); dot = lo + hi;
            val = fmaf(-2.0f, dot, s_c2v[k0 + 3]);
            if (val < minval) { minval = val; mink = k0 + 3; }
        }

        int m = mink / TT;
        int t = mink - m * TT;
        long long NN = N;
        // best_t
        out[n] = s_tc[t];
        // best_e [N, C] at offset N
        {
            float2* eo = (float2*)(out + NN + n * CC);
            const float* lrow = s_lib + m * CC;
#pragma unroll
            for (int j = 0; j < CP; j++)
                eo[j] = make_float2(lrow[2 * j], lrow[2 * j + 1]);
        }
        // best_v at 55N, beta at 56N, texture at 57N
        out[55 * NN + n] = 0.5f;
        out[56 * NN + n] = 0.0f;
        out[57 * NN + n] = s_lm[m];
        // s_recon [N, C] at 58N  (== best candidate spectrum)
        {
            float2* ro = (float2*)(out + 58 * NN + n * CC);
#pragma unroll
            for (int j = 0; j < CP; j++) {
                float x, y;
                unpack2(s_cand[j * NCAND + mink], x, y);
                ro[j] = make_float2(x, y);
            }
        }
        bl = s2sum + minval; // best_loss
    }

    // Block reduction of best_loss for the objective
    red[tid] = bl;
    __syncthreads();
#pragma unroll
    for (int s = 128; s > 0; s >>= 1) {
        if (tid < s) red[tid] += red[tid + s];
        __syncthreads();
    }
    if (tid == 0) atomicAdd(&g_obj, (double)red[0]);
}

__global__ void hadar_finalize(float* __restrict__ out, int N) {
    out[112LL * N] = (float)(g_obj / (double)N);
}

// ---------------------------------------------------------------------------
extern "C" void kernel_launch(void* const* d_in, const int* in_sizes, int n_in,
                              void* d_out, int out_size) {
    const float* s_obs    = (const float*)d_in[0];
    const float* s_sky    = (const float*)d_in[1];
    const float* s_ground = (const float*)d_in[2];
    const float* library  = (const float*)d_in[3];
    const float* wg       = (const float*)d_in[4];
    float* out = (float*)d_out;
    int C = in_sizes[1];           // 54
    int N = in_sizes[0] / C;       // 1048576

    hadar_setup<<<1, 256>>>(s_sky, s_ground, library, wg);
    int blocks = (N + 255) / 256;
    hadar_main<<<blocks, 256>>>(s_obs, library, out, N);
    hadar_finalize<<<1, 1>>>(out, N);
}

// round 3
// speedup vs baseline: 1.4489x; 1.4489x over previous
#include <cuda_runtime.h>

// Problem constants (fixed by reference)
#define CC   54          // channels
#define CP   27          // channel pairs (54/2)
#define MM   6           // materials
#define TT   20          // temperatures
#define NCAND 120        // M*T candidates
#define CTPAD 56         // padded row for candidate-major float table
#define C1F  1.191042e-8f
#define C2F  1.4387752f

// Device-global scratch (no allocations allowed)
__device__ __align__(16) unsigned long long g_cand2[CP * NCAND]; // packed pairs, layout [j][k]
__device__ __align__(16) float g_candT[NCAND * CTPAD];           // candidate-major floats
__device__ float  g_c2[NCAND];
__device__ float  g_tc[TT];
__device__ float  g_lm[MM];
__device__ double g_obj;

__device__ __forceinline__ unsigned long long pack2(float x, float y) {
    unsigned long long r;
    asm("mov.b64 %0, {%1,%2};" : "=l"(r) : "f"(x), "f"(y));
    return r;
}
__device__ __forceinline__ void unpack2(unsigned long long v, float& x, float& y) {
    asm("mov.b64 {%0,%1}, %2;" : "=f"(x), "=f"(y) : "l"(v));
}
__device__ __forceinline__ void fma2(unsigned long long& d, unsigned long long a, unsigned long long b) {
    asm("fma.rn.f32x2 %0, %1, %2, %0;" : "+l"(d) : "l"(a), "l"(b));
}

// ---------------------------------------------------------------------------
// Setup: build candidate spectra (both layouts), norms, t_cand, lib means.
// ---------------------------------------------------------------------------
__global__ void hadar_setup(const float* __restrict__ s_sky,
                            const float* __restrict__ s_ground,
                            const float* __restrict__ library,
                            const float* __restrict__ wg) {
    __shared__ float sh_xamb[CC];
    __shared__ float sh_B[TT][CC];
    __shared__ float sh_lib[MM][CC];
    int tid = threadIdx.x;
    if (tid == 0) g_obj = 0.0;
    for (int c = tid; c < CC; c += blockDim.x)
        sh_xamb[c] = 0.5f * s_sky[c] + 0.5f * s_ground[c];
    for (int i = tid; i < MM * CC; i += blockDim.x)
        sh_lib[i / CC][i % CC] = library[i];
    for (int i = tid; i < TT * CC; i += blockDim.x) {
        int t = i / CC, c = i % CC;
        float Tk = 250.0f + (100.0f / 19.0f) * (float)t;
        float nu = wg[c];
        sh_B[t][c] = C1F * nu * nu * nu / expm1f(C2F * nu / Tk);
    }
    if (tid < TT) g_tc[tid] = 250.0f + (100.0f / 19.0f) * (float)tid;
    __syncthreads();
    if (tid < MM) {
        float s = 0.0f;
        for (int c = 0; c < CC; c++) s += sh_lib[tid][c];
        g_lm[tid] = s / (float)CC;
    }
    for (int i = tid; i < NCAND * CP; i += blockDim.x) {
        int k = i / CP, j = i % CP;
        int m = k / TT, t = k % TT;
        int c0 = 2 * j;
        float e0 = sh_lib[m][c0], e1 = sh_lib[m][c0 + 1];
        float v0 = e0 * sh_B[t][c0]     + (1.0f - e0) * sh_xamb[c0];
        float v1 = e1 * sh_B[t][c0 + 1] + (1.0f - e1) * sh_xamb[c0 + 1];
        g_cand2[j * NCAND + k] = pack2(v0, v1);
        g_candT[k * CTPAD + c0]     = v0;
        g_candT[k * CTPAD + c0 + 1] = v1;
    }
    for (int k = tid; k < NCAND; k += blockDim.x) {
        int m = k / TT, t = k % TT;
        float s = 0.0f;
        for (int c = 0; c < CC; c++) {
            float e = sh_lib[m][c];
            float v = e * sh_B[t][c] + (1.0f - e) * sh_xamb[c];
            s += v * v;
        }
        g_c2[k] = s;
    }
}

// ---------------------------------------------------------------------------
// Main: 2 pixels per thread; argmin over 120 candidates; coalesced outputs.
// Block = 256 threads handles 512 pixels.
// ---------------------------------------------------------------------------
__global__ __launch_bounds__(256)
void hadar_main(const float* __restrict__ s_obs,
                const float* __restrict__ library,
                float* __restrict__ out, int N) {
    __shared__ __align__(16) unsigned long long s_cand[CP * NCAND]; // ~25.9 KB
    __shared__ float s_c2v[NCAND];
    __shared__ float s_tc[TT];
    __shared__ float s_lm[MM];
    __shared__ float s_lib[MM * CC];
    __shared__ int   smink[512];
    __shared__ float red[256];

    int tid = threadIdx.x;
    for (int i = tid; i < CP * NCAND; i += 256) s_cand[i] = g_cand2[i];
    for (int i = tid; i < NCAND; i += 256) s_c2v[i] = g_c2[i];
    for (int i = tid; i < MM * CC; i += 256) s_lib[i] = library[i];
    if (tid < TT) s_tc[tid] = g_tc[tid];
    if (tid < MM) s_lm[tid] = g_lm[tid];
    __syncthreads();

    long long base = (long long)blockIdx.x * 512;
    long long nA = base + tid;         // pixel A
    long long nB = base + 256 + tid;   // pixel B
    bool okA = nA < N, okB = nB < N;
    long long NN = N;
    float bl = 0.0f;

    // Load s_obs rows as packed pairs
    unsigned long long sA[CP], sB[CP];
    float s2A = 0.0f, s2B = 0.0f;
    {
        const float2* pA = (const float2*)(s_obs + (okA ? nA : 0) * CC);
        const float2* pB = (const float2*)(s_obs + (okB ? nB : 0) * CC);
#pragma unroll
        for (int j = 0; j < CP; j++) {
            float2 va = pA[j];
            float2 vb = pB[j];
            s2A = fmaf(va.x, va.x, fmaf(va.y, va.y, s2A));
            s2B = fmaf(vb.x, vb.x, fmaf(vb.y, vb.y, s2B));
            sA[j] = pack2(va.x, va.y);
            sB[j] = pack2(vb.x, vb.y);
        }
    }

    float minA = 3.402823e38f, minB = 3.402823e38f;
    int kA = 0, kB = 0;
#pragma unroll 1
    for (int k0 = 0; k0 < NCAND; k0 += 4) {
        unsigned long long a0 = 0ULL, a1 = 0ULL, a2 = 0ULL, a3 = 0ULL;
        unsigned long long b0 = 0ULL, b1 = 0ULL, b2 = 0ULL, b3 = 0ULL;
#pragma unroll
        for (int j = 0; j < CP; j++) {
            const ulonglong2* row = (const ulonglong2*)(s_cand + j * NCAND + k0);
            ulonglong2 p = row[0];
            ulonglong2 q = row[1];
            fma2(a0, sA[j], p.x);
            fma2(b0, sB[j], p.x);
            fma2(a1, sA[j], p.y);
            fma2(b1, sB[j], p.y);
            fma2(a2, sA[j], q.x);
            fma2(b2, sB[j], q.x);
            fma2(a3, sA[j], q.y);
            fma2(b3, sB[j], q.y);
        }
        float lo, hi, val;
#pragma unroll
        for (int u = 0; u < 4; u++) {
            unsigned long long aa = (u == 0) ? a0 : (u == 1) ? a1 : (u == 2) ? a2 : a3;
            unsigned long long bb = (u == 0) ? b0 : (u == 1) ? b1 : (u == 2) ? b2 : b3;
            float c2v = s_c2v[k0 + u];
            unpack2(aa, lo, hi);
            val = fmaf(-2.0f, lo + hi, c2v);
            if (val < minA) { minA = val; kA = k0 + u; }
            unpack2(bb, lo, hi);
            val = fmaf(-2.0f, lo + hi, c2v);
            if (val < minB) { minB = val; kB = k0 + u; }
        }
    }

    smink[tid] = kA;
    smink[256 + tid] = kB;

    // Scalar outputs (coalesced per instruction)
    if (okA) {
        int m = kA / TT;
        out[nA] = s_tc[kA - m * TT];
        out[55 * NN + nA] = 0.5f;
        out[56 * NN + nA] = 0.0f;
        out[57 * NN + nA] = s_lm[m];
        bl += s2A + minA;
    }
    if (okB) {
        int m = kB / TT;
        out[nB] = s_tc[kB - m * TT];
        out[55 * NN + nB] = 0.5f;
        out[56 * NN + nB] = 0.0f;
        out[57 * NN + nB] = s_lm[m];
        bl += s2B + minB;
    }
    __syncthreads();

    // Cooperative, fully coalesced writes of best_e [N,C] and s_recon [N,C].
    // Element i covers (pixel p = i/27, pair jj = i%27); address = base*54 + 2*i
    // which is consecutive across i -> consecutive lanes.
    {
        float* eo = out + NN + base * CC;        // best_e region for this block
        float* ro = out + 58 * NN + base * CC;   // s_recon region for this block
        int limit = (int)((N - base) < 512 ? (N - base) : 512) * CP;
#pragma unroll 1
        for (int i = tid; i < 512 * CP; i += 256) {
            if (i >= limit) break;
            int p = i / CP;
            int jj = i - p * CP;
            int k = smink[p];
            int m = k / TT;
            float2 e = *(const float2*)(s_lib + m * CC + 2 * jj);
            float2 r = __ldg((const float2*)(g_candT + k * CTPAD + 2 * jj));
            ((float2*)eo)[i] = e;
            ((float2*)ro)[i] = r;
        }
    }

    // Block reduction of best_loss for the objective
    red[tid] = bl;
    __syncthreads();
#pragma unroll
    for (int s = 128; s > 0; s >>= 1) {
        if (tid < s) red[tid] += red[tid + s];
        __syncthreads();
    }
    if (tid == 0) atomicAdd(&g_obj, (double)red[0]);
}

__global__ void hadar_finalize(float* __restrict__ out, int N) {
    out[112LL * N] = (float)(g_obj / (double)N);
}

// ---------------------------------------------------------------------------
extern "C" void kernel_launch(void* const* d_in, const int* in_sizes, int n_in,
                              void* d_out, int out_size) {
    const float* s_obs    = (const float*)d_in[0];
    const float* s_sky    = (const float*)d_in[1];
    const float* s_ground = (const float*)d_in[2];
    const float* library  = (const float*)d_in[3];
    const float* wg       = (const float*)d_in[4];
    float* out = (float*)d_out;
    int C = in_sizes[1];           // 54
    int N = in_sizes[0] / C;       // 1048576

    hadar_setup<<<1, 512>>>(s_sky, s_ground, library, wg);
    int blocks = (N + 511) / 512;
    hadar_main<<<blocks, 256>>>(s_obs, library, out, N);
    hadar_finalize<<<1, 1>>>(out, N);
}